// round 17
// baseline (speedup 1.0000x reference)
#include <cuda_runtime.h>
#include <cuda_bf16.h>
#include <cstdint>

#define NSTEPS 64
#define DD 16
#define THREADS 256
#define WARPS (THREADS / 32)
#define ROWS_PER_WARP 64
#define ROWS_PER_CTA (WARPS * ROWS_PER_WARP)    // 512 (divides 2^21 exactly)
#define WEIGHT_VALS (NSTEPS * DD * DD)          // 16384 per tensor
// smem: WT bf16 (32KB) + VT bf16 (32KB) = 64KB, both transposed [n][k] per step
#define SMEM_BYTES (2 * WEIGHT_VALS * 2)

typedef unsigned long long u64;
typedef unsigned int u32;

// (lo, hi) -> bf16x2 register, lo in low 16 bits
__device__ __forceinline__ u32 to_bf16x2(float lo, float hi) {
    u32 r;
    asm("cvt.rn.bf16x2.f32 %0, %1, %2;" : "=r"(r) : "f"(hi), "f"(lo));
    return r;
}
// ---- bf16x2 packed math (fma pipe) + hardware tanh (MUFU, 2 lanes/op) ----
__device__ __forceinline__ u32 mul_bf2(u32 a, u32 b) {
    u32 d;
    asm("mul.rn.bf16x2 %0, %1, %2;" : "=r"(d) : "r"(a), "r"(b));
    return d;
}
__device__ __forceinline__ u32 fma_bf2(u32 a, u32 b, u32 c) {
    u32 d;
    asm("fma.rn.bf16x2 %0, %1, %2, %3;" : "=r"(d) : "r"(a), "r"(b), "r"(c));
    return d;
}
__device__ __forceinline__ u32 tanh_bf2(u32 a) {
    u32 d;
    asm("tanh.approx.bf16x2 %0, %1;" : "=r"(d) : "r"(a));
    return d;
}

// m16n8k16 bf16 mma, f32 accumulate. A row-major, B col-major.
__device__ __forceinline__ void mma_bf16(
    float& d0, float& d1, float& d2, float& d3,
    u32 a0, u32 a1, u32 a2, u32 a3, u32 b0, u32 b1,
    float c0, float c1, float c2, float c3)
{
    asm("mma.sync.aligned.m16n8k16.row.col.f32.bf16.bf16.f32 "
        "{%0,%1,%2,%3}, {%4,%5,%6,%7}, {%8,%9}, {%10,%11,%12,%13};"
        : "=f"(d0), "=f"(d1), "=f"(d2), "=f"(d3)
        : "r"(a0), "r"(a1), "r"(a2), "r"(a3), "r"(b0), "r"(b1),
          "f"(c0), "f"(c1), "f"(c2), "f"(c3));
}

// tanh-GELU, fully packed bf16x2: input bf16x2 pair -> gelu(pair) bf16x2.
// gelu(x) = 0.5x(1 + tanh(x*(T1 + T2*x^2))); 5 fma-pipe ops + 1 MUFU per pair.
#define GELU_T1 0.7978845608f
#define GELU_T2 0.0356774081f
__device__ __forceinline__ u32 gelu_bf2(u32 x, u32 t1, u32 t2, u32 hf) {
    u32 u = mul_bf2(x, x);          // x^2
    u32 w = fma_bf2(u, t2, t1);     // T1 + T2*x^2
    u32 z = mul_bf2(x, w);          // tanh argument
    u32 t = tanh_bf2(z);            // tanh(z)  (1 MUFU, both lanes)
    u32 hx = mul_bf2(x, hf);        // 0.5x
    return fma_bf2(hx, t, hx);      // 0.5x(1+tanh)
}

__global__ __launch_bounds__(THREADS, 2)
void resnet_steps_kernel(const float* __restrict__ x,
                         const float* __restrict__ W,
                         const float* __restrict__ V,
                         float* __restrict__ out)
{
    extern __shared__ __nv_bfloat16 sbf[];  // [0,16384): W^T ; [16384,32768): (V/64)^T
    const int tid = threadIdx.x;

    // Fill smem: per step s, store transposed [n][k] bf16. V pre-scaled by 1/64.
    {
        const float invn = 1.0f / (float)NSTEPS;
        for (int i = tid; i < WEIGHT_VALS; i += THREADS) {
            int s = i >> 8;
            int rem = i & 255;
            int k = rem >> 4;
            int n = rem & 15;
            int tidx = s * 256 + n * 16 + k;
            sbf[tidx] = __float2bfloat16(W[i]);                 // W[s][k][n]
            sbf[WEIGHT_VALS + tidx] = __float2bfloat16(V[i] * invn);
        }
    }
    __syncthreads();

    const u32 gt1 = to_bf16x2(GELU_T1, GELU_T1);
    const u32 gt2 = to_bf16x2(GELU_T2, GELU_T2);
    const u32 ghf = to_bf16x2(0.5f, 0.5f);

    const int warp = tid >> 5;
    const int lane = tid & 31;
    const int gid = lane >> 2;    // groupID 0..7
    const int tig = lane & 3;     // thread-in-group 0..3

    const int rbase = blockIdx.x * ROWS_PER_CTA + warp * ROWS_PER_WARP;

    // h fragments: h[mt][nt][4] f32 — D-layout of m16n8 tiles.
    float h[4][2][4];
    #pragma unroll
    for (int mt = 0; mt < 4; mt++) {
        #pragma unroll
        for (int nt = 0; nt < 2; nt++) {
            int row0 = rbase + mt * 16 + gid;
            int col = nt * 8 + tig * 2;
            float2 v0 = *reinterpret_cast<const float2*>(x + row0 * DD + col);
            float2 v1 = *reinterpret_cast<const float2*>(x + (row0 + 8) * DD + col);
            h[mt][nt][0] = v0.x; h[mt][nt][1] = v0.y;
            h[mt][nt][2] = v1.x; h[mt][nt][3] = v1.y;
        }
    }

    const u32* wt = reinterpret_cast<const u32*>(sbf);                    // 8192 u32
    const u32* vt = reinterpret_cast<const u32*>(sbf) + WEIGHT_VALS / 2;

    #pragma unroll 1
    for (int s = 0; s < NSTEPS; s++) {
        // B fragments from transposed bf16 weights: 8 conflict-free LDS.32.
        int bidx = s * 128 + gid * 8 + tig;
        u32 bw00 = wt[bidx];        // nt0, k 2tig..+1
        u32 bw01 = wt[bidx + 4];    // nt0, k 2tig+8..
        u32 bw10 = wt[bidx + 64];   // nt1
        u32 bw11 = wt[bidx + 68];
        u32 bv00 = vt[bidx];
        u32 bv01 = vt[bidx + 4];
        u32 bv10 = vt[bidx + 64];
        u32 bv11 = vt[bidx + 68];

        #pragma unroll
        for (int mt = 0; mt < 4; mt++) {
            // A fragment of h (m16k16): lane-local cvt from D-layout (k-cols = n-cols)
            u32 a0 = to_bf16x2(h[mt][0][0], h[mt][0][1]);
            u32 a1 = to_bf16x2(h[mt][0][2], h[mt][0][3]);
            u32 a2 = to_bf16x2(h[mt][1][0], h[mt][1][1]);
            u32 a3 = to_bf16x2(h[mt][1][2], h[mt][1][3]);

            // g = h @ W_s  (two n-tiles)
            float g00, g01, g02, g03, g10, g11, g12, g13;
            mma_bf16(g00, g01, g02, g03, a0, a1, a2, a3, bw00, bw01,
                     0.0f, 0.0f, 0.0f, 0.0f);
            mma_bf16(g10, g11, g12, g13, a0, a1, a2, a3, bw10, bw11,
                     0.0f, 0.0f, 0.0f, 0.0f);

            // cvt to bf16x2 first, then gelu in packed bf16 — the result IS
            // the A-fragment of the second mma (no packing movs).
            u32 e0 = gelu_bf2(to_bf16x2(g00, g01), gt1, gt2, ghf);
            u32 e1 = gelu_bf2(to_bf16x2(g02, g03), gt1, gt2, ghf);
            u32 e2 = gelu_bf2(to_bf16x2(g10, g11), gt1, gt2, ghf);
            u32 e3 = gelu_bf2(to_bf16x2(g12, g13), gt1, gt2, ghf);

            // h += gelu(g) @ (V_s/64)  — C-accumulate is the residual add
            mma_bf16(h[mt][0][0], h[mt][0][1], h[mt][0][2], h[mt][0][3],
                     e0, e1, e2, e3, bv00, bv01,
                     h[mt][0][0], h[mt][0][1], h[mt][0][2], h[mt][0][3]);
            mma_bf16(h[mt][1][0], h[mt][1][1], h[mt][1][2], h[mt][1][3],
                     e0, e1, e2, e3, bv10, bv11,
                     h[mt][1][0], h[mt][1][1], h[mt][1][2], h[mt][1][3]);
        }
    }

    // Store h fragments
    #pragma unroll
    for (int mt = 0; mt < 4; mt++) {
        #pragma unroll
        for (int nt = 0; nt < 2; nt++) {
            int row0 = rbase + mt * 16 + gid;
            int col = nt * 8 + tig * 2;
            float2 v0 = make_float2(h[mt][nt][0], h[mt][nt][1]);
            float2 v1 = make_float2(h[mt][nt][2], h[mt][nt][3]);
            *reinterpret_cast<float2*>(out + row0 * DD + col) = v0;
            *reinterpret_cast<float2*>(out + (row0 + 8) * DD + col) = v1;
        }
    }
}

extern "C" void kernel_launch(void* const* d_in, const int* in_sizes, int n_in,
                              void* d_out, int out_size) {
    const float* x = (const float*)d_in[0];
    const float* W = (const float*)d_in[1];
    const float* V = (const float*)d_in[2];
    float* out = (float*)d_out;

    static bool attr_set = false;
    if (!attr_set) {
        cudaFuncSetAttribute(resnet_steps_kernel,
                             cudaFuncAttributeMaxDynamicSharedMemorySize, SMEM_BYTES);
        attr_set = true;
    }

    const long long batch = (long long)in_sizes[0] / DD;   // 2^21
    const int grid = (int)(batch / ROWS_PER_CTA);          // 4096, exact
    resnet_steps_kernel<<<grid, THREADS, SMEM_BYTES>>>(x, W, V, out);
}